// round 1
// baseline (speedup 1.0000x reference)
#include <cuda_runtime.h>
#include <cuda_bf16.h>
#include <cstdint>

#define BD      8
#define SD      1024
#define HD      16
#define DK      64
#define DM      1024
#define TOPK    32

// ---------------- scratch (static device globals; allocation-free) ----------------
__device__ float g_q[BD * HD * SD * DK];     // [b,h,s,d]
__device__ float g_k[BD * HD * SD * DK];
__device__ float g_v[BD * HD * SD * DK];
__device__ float g_vsum[BD * HD * DK];

// =====================================================================
// Kernel 1: fused projection GEMM  C[8192,1024] = X @ W + b  (x3)
// tile 128x128x16, 256 threads, 8x8 per thread
// =====================================================================
__global__ __launch_bounds__(256) void proj_kernel(
    const float* __restrict__ Xq, const float* __restrict__ Xk, const float* __restrict__ Xv,
    const float* __restrict__ Wq, const float* __restrict__ bq,
    const float* __restrict__ Wk, const float* __restrict__ bk,
    const float* __restrict__ Wv, const float* __restrict__ bv)
{
    __shared__ float As[16][132];   // [k][m], padded
    __shared__ float Bs[16][128];   // [k][n]

    const int p  = blockIdx.x >> 3;           // 0=q 1=k 2=v
    const int n0 = (blockIdx.x & 7) * 128;
    const int m0 = blockIdx.y * 128;

    const float* X    = (p == 0) ? Xq : (p == 1) ? Xk : Xv;
    const float* W    = (p == 0) ? Wq : (p == 1) ? Wk : Wv;
    const float* bias = (p == 0) ? bq : (p == 1) ? bk : bv;
    float* out        = (p == 0) ? g_q : (p == 1) ? g_k : g_v;

    const int tid = threadIdx.x;
    const int tx  = tid & 15;
    const int ty  = tid >> 4;

    float acc[8][8];
#pragma unroll
    for (int i = 0; i < 8; i++)
#pragma unroll
        for (int j = 0; j < 8; j++) acc[i][j] = 0.0f;

    const int ar = tid >> 2;          // 0..63
    const int ac = (tid & 3) * 4;     // 0,4,8,12
    const int br = tid >> 5;          // 0..7
    const int bc = (tid & 31) * 4;    // 0..124

    for (int k0 = 0; k0 < DM; k0 += 16) {
        float4 a0 = *(const float4*)(X + (size_t)(m0 + ar) * DM + k0 + ac);
        float4 a1 = *(const float4*)(X + (size_t)(m0 + ar + 64) * DM + k0 + ac);
        float4 b0 = *(const float4*)(W + (size_t)(k0 + br) * DM + n0 + bc);
        float4 b1 = *(const float4*)(W + (size_t)(k0 + br + 8) * DM + n0 + bc);

        __syncthreads();
        As[ac + 0][ar] = a0.x; As[ac + 1][ar] = a0.y; As[ac + 2][ar] = a0.z; As[ac + 3][ar] = a0.w;
        As[ac + 0][ar + 64] = a1.x; As[ac + 1][ar + 64] = a1.y; As[ac + 2][ar + 64] = a1.z; As[ac + 3][ar + 64] = a1.w;
        *(float4*)&Bs[br][bc]     = b0;
        *(float4*)&Bs[br + 8][bc] = b1;
        __syncthreads();

#pragma unroll
        for (int kk = 0; kk < 16; kk++) {
            float4 aA = *(const float4*)&As[kk][ty * 4];
            float4 aB = *(const float4*)&As[kk][64 + ty * 4];
            float4 bA = *(const float4*)&Bs[kk][tx * 4];
            float4 bB = *(const float4*)&Bs[kk][64 + tx * 4];
            float av[8] = {aA.x, aA.y, aA.z, aA.w, aB.x, aB.y, aB.z, aB.w};
            float bv_[8] = {bA.x, bA.y, bA.z, bA.w, bB.x, bB.y, bB.z, bB.w};
#pragma unroll
            for (int i = 0; i < 8; i++)
#pragma unroll
                for (int j = 0; j < 8; j++) acc[i][j] = fmaf(av[i], bv_[j], acc[i][j]);
        }
    }

#pragma unroll
    for (int i = 0; i < 8; i++) {
        int m = m0 + ((i < 4) ? (ty * 4 + i) : (64 + ty * 4 + i - 4));
        int bb = m >> 10, s = m & 1023;
#pragma unroll
        for (int j = 0; j < 8; j++) {
            int n = n0 + ((j < 4) ? (tx * 4 + j) : (64 + tx * 4 + j - 4));
            int h = n >> 6, d = n & 63;
            out[((size_t)(bb * HD + h) * SD + s) * DK + d] = acc[i][j] + bias[n];
        }
    }
}

// =====================================================================
// Kernel 2: Vsum[bh][d] = sum_s v[bh][s][d]
// =====================================================================
__global__ __launch_bounds__(256) void vsum_kernel()
{
    __shared__ float red[4][64];
    const int bh = blockIdx.x;
    const int d  = threadIdx.x & 63;
    const int c  = threadIdx.x >> 6;            // 0..3
    const float* vp = g_v + (size_t)bh * SD * DK + (size_t)c * 256 * DK + d;
    float s = 0.0f;
#pragma unroll 8
    for (int i = 0; i < 256; i++) s += vp[i * DK];
    red[c][d] = s;
    __syncthreads();
    if (c == 0) g_vsum[bh * DK + d] = red[0][d] + red[1][d] + red[2][d] + red[3][d];
}

// =====================================================================
// Kernel 3: fused scores + exact top-32 + context
// block = 256 threads, 16 query rows, one (b,h)
// =====================================================================
#define KS_PAD 516
// floats: sc 16*1024 | qs 64*16 | ks 16*516 | top_i 16*32 | top_w 16*32
#define ATT_SMEM_FLOATS (16 * 1024 + 64 * 16 + 16 * KS_PAD + 16 * 32 + 16 * 32)
#define ATT_SMEM_BYTES  (ATT_SMEM_FLOATS * 4)

__global__ __launch_bounds__(256, 2) void attn_kernel(float* __restrict__ out)
{
    extern __shared__ float smem[];
    float (*sc)[1024]   = (float(*)[1024])smem;
    float (*qs)[16]     = (float(*)[16])(smem + 16 * 1024);
    float (*ks)[KS_PAD] = (float(*)[KS_PAD])(smem + 16 * 1024 + 64 * 16);
    int   (*top_i)[32]  = (int(*)[32])(smem + 16 * 1024 + 64 * 16 + 16 * KS_PAD);
    float (*top_w)[32]  = (float(*)[32])(smem + 16 * 1024 + 64 * 16 + 16 * KS_PAD + 16 * 32);

    const int bh  = blockIdx.y;
    const int q0  = blockIdx.x * 16;
    const int tid = threadIdx.x;

    const float* qptr = g_q + (size_t)bh * SD * DK;
    const float* kptr = g_k + (size_t)bh * SD * DK;
    const float* vptr = g_v + (size_t)bh * SD * DK;

    // ---- load q tile transposed: qs[d][row], rows q0..q0+15 ----
    {
        int row = tid & 15;
        int dq  = (tid >> 4) * 4;  // 0..60
        float4 v4 = *(const float4*)(qptr + (size_t)(q0 + row) * DK + dq);
        qs[dq + 0][row] = v4.x; qs[dq + 1][row] = v4.y;
        qs[dq + 2][row] = v4.z; qs[dq + 3][row] = v4.w;
    }

    const int ty = tid >> 6;   // 0..3  (q-row group)
    const int tx = tid & 63;   // 0..63 (k-col group)

    // ---- Phase 1: scores[16][1024] = q @ k^T ----
    for (int nc = 0; nc < 2; nc++) {
        float acc[4][8];
#pragma unroll
        for (int i = 0; i < 4; i++)
#pragma unroll
            for (int j = 0; j < 8; j++) acc[i][j] = 0.0f;

        for (int dc = 0; dc < 4; dc++) {
            __syncthreads();   // protect ks reuse (and qs on first pass)
            {
                int rbase = tid >> 2;
                int quad  = (tid & 3) * 4;
#pragma unroll
                for (int r8 = 0; r8 < 8; r8++) {
                    int row = rbase + r8 * 64;
                    float4 kv = *(const float4*)(kptr + (size_t)(nc * 512 + row) * DK + dc * 16 + quad);
                    ks[quad + 0][row] = kv.x; ks[quad + 1][row] = kv.y;
                    ks[quad + 2][row] = kv.z; ks[quad + 3][row] = kv.w;
                }
            }
            __syncthreads();
#pragma unroll
            for (int kk = 0; kk < 16; kk++) {
                float4 qa  = *(const float4*)&qs[dc * 16 + kk][ty * 4];
                float4 k0v = *(const float4*)&ks[kk][tx * 8];
                float4 k1v = *(const float4*)&ks[kk][tx * 8 + 4];
                float qv[4] = {qa.x, qa.y, qa.z, qa.w};
                float kv[8] = {k0v.x, k0v.y, k0v.z, k0v.w, k1v.x, k1v.y, k1v.z, k1v.w};
#pragma unroll
                for (int i = 0; i < 4; i++)
#pragma unroll
                    for (int j = 0; j < 8; j++) acc[i][j] = fmaf(qv[i], kv[j], acc[i][j]);
            }
        }
#pragma unroll
        for (int i = 0; i < 4; i++) {
            *(float4*)&sc[ty * 4 + i][nc * 512 + tx * 8]     = make_float4(acc[i][0], acc[i][1], acc[i][2], acc[i][3]);
            *(float4*)&sc[ty * 4 + i][nc * 512 + tx * 8 + 4] = make_float4(acc[i][4], acc[i][5], acc[i][6], acc[i][7]);
        }
    }
    __syncthreads();

    // ---- Phase 2+3: per warp, 2 rows: exact top-32 + context ----
    const int warp = tid >> 5;
    const int lane = tid & 31;
    const unsigned lmask_lt = (1u << lane) - 1u;
    const int bb = bh >> 4;
    const int h  = bh & 15;

    for (int rr = 0; rr < 2; rr++) {
        const int row = warp * 2 + rr;

        // scaled scores -> order-preserving uint keys
        unsigned key[32];
#pragma unroll
        for (int i = 0; i < 32; i++) {
            float s = sc[row][lane + 32 * i] * 0.125f;
            unsigned ub = __float_as_uint(s);
            key[i] = (ub & 0x80000000u) ? ~ub : (ub | 0x80000000u);
        }

        // MSB-first binary search for the 32nd-largest key (early exit at count==32)
        unsigned T = 0u;
        bool done = false;
        for (int bit = 31; bit >= 0 && !done; --bit) {
            unsigned cand = T | (1u << bit);
            int c = 0;
#pragma unroll
            for (int i = 0; i < 32; i++) c += (key[i] >= cand) ? 1 : 0;
#pragma unroll
            for (int o = 16; o > 0; o >>= 1) c += __shfl_xor_sync(0xffffffffu, c, o);
            if (c >= TOPK) { T = cand; if (c == TOPK) done = true; }
        }

        // compaction: strictly-greater first, then ties in index order
        int base = 0;
#pragma unroll
        for (int i = 0; i < 32; i++) {
            bool sel = key[i] > T;
            unsigned m = __ballot_sync(0xffffffffu, sel);
            if (sel) {
                int pos = base + __popc(m & lmask_lt);
                unsigned ub = (key[i] & 0x80000000u) ? (key[i] & 0x7fffffffu) : ~key[i];
                top_i[row][pos] = lane + 32 * i;
                top_w[row][pos] = __expf(__uint_as_float(ub));
            }
            base += __popc(m);
        }
        for (int i = 0; i < 32 && base < TOPK; i++) {
            bool sel = (key[i] == T);
            unsigned m = __ballot_sync(0xffffffffu, sel);
            if (sel) {
                int pos = base + __popc(m & lmask_lt);
                if (pos < TOPK) {
                    unsigned ub = (key[i] & 0x80000000u) ? (key[i] & 0x7fffffffu) : ~key[i];
                    top_i[row][pos] = lane + 32 * i;
                    top_w[row][pos] = __expf(__uint_as_float(ub));
                }
            }
            base += __popc(m);
        }
        __syncwarp();

        // denominator: (S - K)*exp(0) + sum(exp(topk)) + 1e-8
        float wsum = top_w[row][lane];
#pragma unroll
        for (int o = 16; o > 0; o >>= 1) wsum += __shfl_xor_sync(0xffffffffu, wsum, o);
        float rden = 1.0f / ((float)(SD - TOPK) + wsum + 1e-8f);

        // context: (Vsum + sum (exp(s)-1) * v_j) / den ; lane owns d = 2*lane, 2*lane+1
        float a0 = g_vsum[bh * DK + lane * 2];
        float a1 = g_vsum[bh * DK + lane * 2 + 1];
#pragma unroll
        for (int t = 0; t < TOPK; t++) {
            int   idx = top_i[row][t];
            float w   = top_w[row][t] - 1.0f;
            float2 vv = *(const float2*)(vptr + (size_t)idx * DK + lane * 2);
            a0 = fmaf(w, vv.x, a0);
            a1 = fmaf(w, vv.y, a1);
        }
        int s_glob = q0 + row;
        float2 o2 = make_float2(a0 * rden, a1 * rden);
        *(float2*)(out + ((size_t)(bb * SD + s_glob) * DM) + h * DK + lane * 2) = o2;
    }
}

// =====================================================================
extern "C" void kernel_launch(void* const* d_in, const int* in_sizes, int n_in,
                              void* d_out, int out_size)
{
    (void)in_sizes; (void)n_in; (void)out_size;
    const float* Q  = (const float*)d_in[0];
    const float* K  = (const float*)d_in[1];
    const float* V  = (const float*)d_in[2];
    const float* Wq = (const float*)d_in[3];
    const float* bq = (const float*)d_in[4];
    const float* Wk = (const float*)d_in[5];
    const float* bk = (const float*)d_in[6];
    const float* Wv = (const float*)d_in[7];
    const float* bv = (const float*)d_in[8];
    float* out = (float*)d_out;

    cudaFuncSetAttribute(attn_kernel, cudaFuncAttributeMaxDynamicSharedMemorySize, ATT_SMEM_BYTES);

    proj_kernel<<<dim3(24, 64), 256>>>(Q, K, V, Wq, bq, Wk, bk, Wv, bv);
    vsum_kernel<<<BD * HD, 256>>>();
    attn_kernel<<<dim3(SD / 16, BD * HD), 256, ATT_SMEM_BYTES>>>(out);
}